// round 14
// baseline (speedup 1.0000x reference)
#include <cuda_runtime.h>
#include <cuda_fp16.h>
#include <cstdint>
#include <cstddef>

#define NN 16384
#define HID 128
#define GG 64

// ---------- static scratch ----------
__device__ __align__(16) uint8_t d_supTf[(NN / 32) * 8192];  // 4 MB fp16 A fragments
__device__ float d_g[GG * HID];

// ---------- helpers ----------
__device__ __forceinline__ uint32_t smem_u32(const void* p) {
    uint32_t a;
    asm("{ .reg .u64 t; cvta.to.shared.u64 t, %1; cvt.u32.u64 %0, t; }" : "=r"(a) : "l"(p));
    return a;
}
__device__ __forceinline__ void cp16(uint32_t dst, const void* src) {
    asm volatile("cp.async.cg.shared.global [%0], [%1], 16;" :: "r"(dst), "l"(src) : "memory");
}
#define CP_COMMIT() asm volatile("cp.async.commit_group;" ::: "memory")
#define CP_WAIT(n)  asm volatile("cp.async.wait_group " #n ";" ::: "memory")

__device__ __forceinline__ void lds128(uint32_t* r, uint32_t a) {
    asm volatile("ld.shared.v4.b32 {%0,%1,%2,%3}, [%4];"
                 : "=r"(r[0]), "=r"(r[1]), "=r"(r[2]), "=r"(r[3]) : "r"(a));
}
__device__ __forceinline__ void lds128f(float* r, uint32_t a) {
    asm volatile("ld.shared.v4.f32 {%0,%1,%2,%3}, [%4];"
                 : "=f"(r[0]), "=f"(r[1]), "=f"(r[2]), "=f"(r[3]) : "r"(a));
}
__device__ __forceinline__ uint32_t lds32(uint32_t a) {
    uint32_t v;
    asm volatile("ld.shared.b32 %0, [%1];" : "=r"(v) : "r"(a));
    return v;
}
__device__ __forceinline__ void sts64(uint32_t a, uint32_t x, uint32_t y) {
    asm volatile("st.shared.v2.b32 [%0], {%1,%2};" :: "r"(a), "r"(x), "r"(y) : "memory");
}
__device__ __forceinline__ uint32_t packh2(float lo, float hi) {
    uint32_t d;
    asm("cvt.rn.f16x2.f32 %0, %1, %2;" : "=r"(d) : "f"(hi), "f"(lo));
    return d;
}
__device__ __forceinline__ void mma16816(float* c, const uint32_t* a, const uint32_t* b) {
    asm volatile(
        "mma.sync.aligned.m16n8k16.row.col.f32.f16.f16.f32 "
        "{%0,%1,%2,%3}, {%4,%5,%6,%7}, {%8,%9}, {%0,%1,%2,%3};"
        : "+f"(c[0]), "+f"(c[1]), "+f"(c[2]), "+f"(c[3])
        : "r"(a[0]), "r"(a[1]), "r"(a[2]), "r"(a[3]), "r"(b[0]), "r"(b[1]));
}
__device__ __forceinline__ float leaky(float v) { return v > 0.f ? v : 0.01f * v; }
__device__ __forceinline__ void atomicMaxFloat(float* addr, float v) {
    if (v >= 0.f) atomicMax((int*)addr, __float_as_int(v));
    else          atomicMin((unsigned int*)addr, __float_as_uint(v));
}

// =============== Kernel 1: supT fp16 fragments = (x @ W_gcn)^T ===============
// Exact R5 version (measured ~24 us). grid 256 = (mblk 128) x (ch 2), 256 thr.
#define K1_WS_OFF   0
#define K1_XB_OFF   32768
#define K1_HS_OFF   (32768 + 3 * 16384)
#define K1_SMEM     (K1_HS_OFF + 64 * 136 * 2)    // 99328

__device__ __forceinline__ void k1_load_chunk(uint32_t sb, const float* __restrict__ x,
                                              int m0, int c, int buf, int tid)
{
    const uint32_t xb = sb + K1_XB_OFF + buf * 16384;
    #pragma unroll
    for (int j = 0; j < 4; j++) {
        int i = tid + (j << 8);            // 0..1023
        int r = i >> 3, q = i & 7;
        cp16(xb + (uint32_t)((r << 7) + ((q ^ (r & 7)) << 4)),
             x + (size_t)(m0 + r) * 128 + c * 32 + q * 4);
    }
    CP_COMMIT();
}

__global__ void __launch_bounds__(256, 2)
gcn_support(const float* __restrict__ x, const float* __restrict__ Wg)
{
    extern __shared__ char sm1[];
    const uint32_t sb = smem_u32(sm1);
    float4* ws = (float4*)sm1;                       // [128 k][16 float4] (ch half)
    __half* hs = (__half*)(sm1 + K1_HS_OFF);         // [64 c][136 nodes]
    const int t = threadIdx.x;
    const int bx = blockIdx.x;
    const int mblk = bx >> 1, ch = bx & 1;
    const int m0 = mblk << 7;

    for (int i = t; i < 128 * 16; i += 256)
        cp16(sb + K1_WS_OFF + i * 16, (const float4*)Wg + (i >> 4) * 32 + ch * 16 + (i & 15));
    k1_load_chunk(sb, x, m0, 0, 0, t);
    k1_load_chunk(sb, x, m0, 1, 1, t);

    if (bx == 0) {
        for (int i = t; i < GG * HID; i += 256)
            d_g[i] = __int_as_float(0xff800000);     // -inf
    }

    const int n = t & 127, cq = t >> 7;
    float acc[32];
    #pragma unroll
    for (int c = 0; c < 32; c++) acc[c] = 0.f;

    for (int c = 0; c < 4; c++) {
        const int rem = 3 - c;
        if (rem >= 1) CP_WAIT(1); else CP_WAIT(0);
        __syncthreads();
        if (c + 2 < 4) k1_load_chunk(sb, x, m0, c + 2, (c + 2) % 3, t);

        const uint32_t xb = sb + K1_XB_OFF + (c % 3) * 16384 + (n << 7);
        #pragma unroll
        for (int k4 = 0; k4 < 8; k4++) {
            float xv[4];
            lds128f(xv, xb + (uint32_t)((k4 ^ (n & 7)) << 4));
            #pragma unroll
            for (int kk = 0; kk < 4; kk++) {
                const float xs = xv[kk];
                const float4* wk = ws + (((c * 32 + (k4 << 2) + kk) << 4) + (cq << 3));
                #pragma unroll
                for (int c4 = 0; c4 < 8; c4++) {
                    float4 w = wk[c4];
                    acc[4 * c4 + 0] += xs * w.x;
                    acc[4 * c4 + 1] += xs * w.y;
                    acc[4 * c4 + 2] += xs * w.z;
                    acc[4 * c4 + 3] += xs * w.w;
                }
            }
        }
        __syncthreads();
    }

    #pragma unroll
    for (int j = 0; j < 32; j++) hs[(cq * 32 + j) * 136 + n] = __float2half_rn(acc[j]);
    __syncthreads();

    const int lam = t & 31;
    for (int fbi = t >> 5; fbi < 32; fbi += 8) {
        const int cl = fbi >> 3, h16l = (fbi >> 1) & 3, g = fbi & 1;
        uint32_t v[4];
        #pragma unroll
        for (int j = 0; j < 4; j++) {
            int row = h16l * 16 + (lam >> 2) + ((j & 1) << 3);
            int kin = (g << 4) + ((lam & 3) << 1) + ((j >> 1) << 3);
            v[j] = *(const uint32_t*)(hs + row * 136 + cl * 32 + kin);
        }
        const int h16 = ch * 4 + h16l;
        const int chunk = mblk * 4 + cl;
        uint4* dst = (uint4*)(d_supTf + (size_t)chunk * 8192 + (size_t)((h16 * 2 + g) << 9) + (lam << 4));
        *dst = make_uint4(v[0], v[1], v[2], v[3]);
    }
}

// ====== Kernel 2: h^T = supT @ adj^T ; bias + leaky + segment-max (fused) ======
// R10/R13 structure, widened to 512 threads (16 warps, 4/SMSP) to hide
// barrier/wait bubbles on the tensor pipe. Same K-order per output element.
#define A_STG     3
#define A_BYTES   16384                   // Kc=64 A fragments
#define B_STG     2
#define B_BYTES   16384                   // 128 nodes x 64k fp16
#define OFF_A     1024
#define OFF_B     (OFF_A + A_STG * A_BYTES)
#define SMEM_K2   (OFF_B + B_STG * B_BYTES)   // 83968
#define NSTAGE    256

__device__ __forceinline__ void issue_A(uint32_t sb, int s, int tid)
{
    const uint32_t aS = sb + OFF_A + (s % A_STG) * A_BYTES;
    const char* aG = (const char*)d_supTf + (size_t)s * A_BYTES;
    #pragma unroll
    for (int j = 0; j < 2; j++)
        cp16(aS + (uint32_t)((tid + (j << 9)) << 4), aG + ((tid + (j << 9)) << 4));
    CP_COMMIT();
}

__global__ void __launch_bounds__(512, 1)
gcn_gemm_pool(const float* __restrict__ adj, const float* __restrict__ b_gcn,
              const int* __restrict__ batch)
{
    extern __shared__ char smem[];
    const uint32_t sb = smem_u32(smem);
    const int tid = threadIdx.x;
    const int wid = tid >> 5, lid = tid & 31;
    const int wr = wid >> 2, wc = wid & 3;       // 4 HID-quarters x 4 node-quarters
    const int m0 = blockIdx.x << 7;

    float4 breg[4];

    float acc[2][4][4];
    #pragma unroll
    for (int a = 0; a < 2; a++)
        #pragma unroll
        for (int b = 0; b < 4; b++)
            #pragma unroll
            for (int c = 0; c < 4; c++) acc[a][b][c] = 0.f;

    // prologue
    issue_A(sb, 0, tid);
    issue_A(sb, 1, tid);
    #pragma unroll
    for (int i = 0; i < 4; i++) {
        const int c = tid + (i << 9);
        const int r = c >> 4, q = c & 15;
        breg[i] = __ldg((const float4*)(adj + (size_t)(m0 + r) * NN + q * 4));
    }

    for (int s = 0; s < NSTAGE; s++) {
        // 1) stage B(s): cvt + STS from regs
        const uint32_t bS = sb + OFF_B + (s & 1) * B_BYTES;
        #pragma unroll
        for (int i = 0; i < 4; i++) {
            const int c = tid + (i << 9);
            const int r = c >> 4, q = c & 15;
            const uint32_t lo = packh2(breg[i].x, breg[i].y);
            const uint32_t hi = packh2(breg[i].z, breg[i].w);
            const uint32_t sw = (uint32_t)((r & 7) << 2);
            sts64(bS + (uint32_t)(r * 128) + ((((uint32_t)(2 * q)) ^ sw) << 2), lo, hi);
        }
        // 2) prefetch B(s+1) into regs
        if (s + 1 < NSTAGE) {
            #pragma unroll
            for (int i = 0; i < 4; i++) {
                const int c = tid + (i << 9);
                const int r = c >> 4, q = c & 15;
                breg[i] = __ldg((const float4*)(adj + (size_t)(m0 + r) * NN +
                                                (size_t)(s + 1) * 64 + q * 4));
            }
        }
        // 3) issue A(s+2)
        if (s + 2 < NSTAGE) issue_A(sb, s + 2, tid);
        // 4) A(s) must be resident; barrier also publishes B(s)
        const int rem = NSTAGE - 1 - s;
        if (rem >= 2)      CP_WAIT(2);
        else if (rem == 1) CP_WAIT(1);
        else               CP_WAIT(0);
        __syncthreads();

        // 5) compute
        const uint32_t aS = sb + OFF_A + (s % A_STG) * A_BYTES;
        #pragma unroll
        for (int ks = 0; ks < 4; ks++) {
            const int cch = ks >> 1, g = ks & 1;
            uint32_t afr[2][4];
            #pragma unroll
            for (int mt = 0; mt < 2; mt++)
                lds128(afr[mt], aS + (uint32_t)(cch * 8192 +
                       ((((wr * 2 + mt) * 2 + g) << 9) + (lid << 4))));
            const int p = (lid & 3) + (g << 3) + (cch << 4);
            uint32_t bfr[4][2];
            #pragma unroll
            for (int nt = 0; nt < 4; nt++) {
                const int mloc = wc * 32 + nt * 8 + (lid >> 2);
                const uint32_t sw = (uint32_t)((mloc & 7) << 2);
                const uint32_t rowb = bS + (uint32_t)(mloc * 128);
                bfr[nt][0] = lds32(rowb + ((((uint32_t)p) ^ sw) << 2));
                bfr[nt][1] = lds32(rowb + ((((uint32_t)(p + 4)) ^ sw) << 2));
            }
            #pragma unroll
            for (int mt = 0; mt < 2; mt++)
                #pragma unroll
                for (int nt = 0; nt < 4; nt++)
                    mma16816(acc[mt][nt], afr[mt], bfr[nt]);
        }
    }

    // epilogue: bias + leaky + segment-max (sign-split int atomics)
    #pragma unroll
    for (int nt = 0; nt < 4; nt++) {
        const int mA = m0 + wc * 32 + nt * 8 + 2 * (lid & 3);
        const int g0 = batch[mA] * HID;
        const int g1 = batch[mA + 1] * HID;
        #pragma unroll
        for (int mt = 0; mt < 2; mt++) {
            const int h0 = wr * 32 + mt * 16 + (lid >> 2);
            const float b0v = b_gcn[h0], b8v = b_gcn[h0 + 8];
            atomicMaxFloat(&d_g[g0 + h0],     leaky(acc[mt][nt][0] + b0v));
            atomicMaxFloat(&d_g[g1 + h0],     leaky(acc[mt][nt][1] + b0v));
            atomicMaxFloat(&d_g[g0 + h0 + 8], leaky(acc[mt][nt][2] + b8v));
            atomicMaxFloat(&d_g[g1 + h0 + 8], leaky(acc[mt][nt][3] + b8v));
        }
    }
}

// =============== Kernel 3: tiny MLP + head (vectorized, ILP) ===============
__global__ void __launch_bounds__(128)
mlp_head(const float* __restrict__ Wl1, const float* __restrict__ bl1,
         const float* __restrict__ Wl2, const float* __restrict__ bl2,
         const float* __restrict__ Wout, const float* __restrict__ bout,
         float* __restrict__ out)
{
    __shared__ float gin[128], h1[128], h2[128];
    const int i = blockIdx.x, t = threadIdx.x;
    gin[t] = d_g[i * HID + t];
    __syncthreads();

    {
        float a = bl1[t];
        const float4* w = (const float4*)(Wl1 + t * 128);
        const float4* g4 = (const float4*)gin;
        #pragma unroll
        for (int k4 = 0; k4 < 32; k4++) {
            const float4 wv = w[k4];
            const float4 gv = g4[k4];
            a += wv.x * gv.x;
            a += wv.y * gv.y;
            a += wv.z * gv.z;
            a += wv.w * gv.w;
        }
        h1[t] = leaky(a);
    }
    __syncthreads();

    {
        float b = bl2[t];
        const float4* w = (const float4*)(Wl2 + t * 128);
        const float4* g4 = (const float4*)h1;
        #pragma unroll
        for (int k4 = 0; k4 < 32; k4++) {
            const float4 wv = w[k4];
            const float4 gv = g4[k4];
            b += wv.x * gv.x;
            b += wv.y * gv.y;
            b += wv.z * gv.z;
            b += wv.w * gv.w;
        }
        h2[t] = leaky(b);
    }
    __syncthreads();

    if (t < 2) {
        float o = bout[t];
        const float4* w = (const float4*)(Wout + t * 128);
        const float4* g4 = (const float4*)h2;
        #pragma unroll
        for (int k4 = 0; k4 < 32; k4++) {
            const float4 wv = w[k4];
            const float4 gv = g4[k4];
            o += wv.x * gv.x;
            o += wv.y * gv.y;
            o += wv.z * gv.z;
            o += wv.w * gv.w;
        }
        out[i * 2 + t] = o;
    }
}

// =============== launch ===============
extern "C" void kernel_launch(void* const* d_in, const int* in_sizes, int n_in,
                              void* d_out, int out_size)
{
    const float* x    = (const float*)d_in[0];
    const float* adj  = (const float*)d_in[1];
    const float* Wg   = (const float*)d_in[2];
    const float* bg   = (const float*)d_in[3];
    const float* Wl1  = (const float*)d_in[4];
    const float* bl1  = (const float*)d_in[5];
    const float* Wl2  = (const float*)d_in[6];
    const float* bl2  = (const float*)d_in[7];
    const float* Wout = (const float*)d_in[8];
    const float* bout = (const float*)d_in[9];
    const int*   batch = (const int*)d_in[10];
    float* out = (float*)d_out;

    cudaFuncSetAttribute(gcn_support,   cudaFuncAttributeMaxDynamicSharedMemorySize, K1_SMEM);
    cudaFuncSetAttribute(gcn_gemm_pool, cudaFuncAttributeMaxDynamicSharedMemorySize, SMEM_K2);

    gcn_support<<<256, 256, K1_SMEM>>>(x, Wg);
    gcn_gemm_pool<<<128, 512, SMEM_K2>>>(adj, bg, batch);
    mlp_head<<<GG, 128>>>(Wl1, bl1, Wl2, bl2, Wout, bout, out);
}

// round 15
// speedup vs baseline: 1.1530x; 1.1530x over previous
#include <cuda_runtime.h>
#include <cuda_fp16.h>
#include <cstdint>
#include <cstddef>

#define NN 16384
#define HID 128
#define GG 64

// ---------- static scratch ----------
__device__ __align__(16) uint8_t d_supTf[(NN / 32) * 8192];  // 4 MB fp16 A fragments
__device__ float d_g[GG * HID];

// ---------- helpers ----------
__device__ __forceinline__ uint32_t smem_u32(const void* p) {
    uint32_t a;
    asm("{ .reg .u64 t; cvta.to.shared.u64 t, %1; cvt.u32.u64 %0, t; }" : "=r"(a) : "l"(p));
    return a;
}
__device__ __forceinline__ void cp16(uint32_t dst, const void* src) {
    asm volatile("cp.async.cg.shared.global [%0], [%1], 16;" :: "r"(dst), "l"(src) : "memory");
}
#define CP_COMMIT() asm volatile("cp.async.commit_group;" ::: "memory")
#define CP_WAIT(n)  asm volatile("cp.async.wait_group " #n ";" ::: "memory")

__device__ __forceinline__ void lds128(uint32_t* r, uint32_t a) {
    asm volatile("ld.shared.v4.b32 {%0,%1,%2,%3}, [%4];"
                 : "=r"(r[0]), "=r"(r[1]), "=r"(r[2]), "=r"(r[3]) : "r"(a));
}
__device__ __forceinline__ void lds128f(float* r, uint32_t a) {
    asm volatile("ld.shared.v4.f32 {%0,%1,%2,%3}, [%4];"
                 : "=f"(r[0]), "=f"(r[1]), "=f"(r[2]), "=f"(r[3]) : "r"(a));
}
__device__ __forceinline__ uint32_t lds32(uint32_t a) {
    uint32_t v;
    asm volatile("ld.shared.b32 %0, [%1];" : "=r"(v) : "r"(a));
    return v;
}
__device__ __forceinline__ void sts64(uint32_t a, uint32_t x, uint32_t y) {
    asm volatile("st.shared.v2.b32 [%0], {%1,%2};" :: "r"(a), "r"(x), "r"(y) : "memory");
}
__device__ __forceinline__ uint32_t packh2(float lo, float hi) {
    uint32_t d;
    asm("cvt.rn.f16x2.f32 %0, %1, %2;" : "=r"(d) : "f"(hi), "f"(lo));
    return d;
}
__device__ __forceinline__ void mma16816(float* c, const uint32_t* a, const uint32_t* b) {
    asm volatile(
        "mma.sync.aligned.m16n8k16.row.col.f32.f16.f16.f32 "
        "{%0,%1,%2,%3}, {%4,%5,%6,%7}, {%8,%9}, {%0,%1,%2,%3};"
        : "+f"(c[0]), "+f"(c[1]), "+f"(c[2]), "+f"(c[3])
        : "r"(a[0]), "r"(a[1]), "r"(a[2]), "r"(a[3]), "r"(b[0]), "r"(b[1]));
}
__device__ __forceinline__ float leaky(float v) { return v > 0.f ? v : 0.01f * v; }
__device__ __forceinline__ void atomicMaxFloat(float* addr, float v) {
    if (v >= 0.f) atomicMax((int*)addr, __float_as_int(v));
    else          atomicMin((unsigned int*)addr, __float_as_uint(v));
}

// =============== Kernel 1: supT fp16 fragments = (x @ W_gcn)^T ===============
// grid 256 = (mblk 128) x (ch 2), 256 thr. Thread tile: 4 nodes x 8 cols
// (W loads 2 LDS.128/k broadcast, x 1 LDS.128/k -> FFMA-bound).
#define K1_WS_OFF   0
#define K1_XB_OFF   32768
#define K1_HS_OFF   (32768 + 3 * 16384)
#define K1_SMEM     (K1_HS_OFF + 64 * 136 * 2)    // 99328

__device__ __forceinline__ void k1_load_chunk(uint32_t sb, const float* __restrict__ x,
                                              int m0, int c, int buf, int tid)
{
    const uint32_t xb = sb + K1_XB_OFF + buf * 16384;
    #pragma unroll
    for (int j = 0; j < 4; j++) {
        int i = tid + (j << 8);            // 0..1023
        int r = i >> 3, q = i & 7;
        cp16(xb + (uint32_t)((r << 7) + ((q ^ (r & 7)) << 4)),
             x + (size_t)(m0 + r) * 128 + c * 32 + q * 4);
    }
    CP_COMMIT();
}

__global__ void __launch_bounds__(256, 2)
gcn_support(const float* __restrict__ x, const float* __restrict__ Wg)
{
    extern __shared__ char sm1[];
    const uint32_t sb = smem_u32(sm1);
    float4* ws = (float4*)sm1;                       // [128 k][16 float4] (ch half)
    __half* hs = (__half*)(sm1 + K1_HS_OFF);         // [64 c][136 nodes]
    const int t = threadIdx.x;
    const int bx = blockIdx.x;
    const int mblk = bx >> 1, ch = bx & 1;
    const int m0 = mblk << 7;

    for (int i = t; i < 128 * 16; i += 256)
        cp16(sb + K1_WS_OFF + i * 16, (const float4*)Wg + (i >> 4) * 32 + ch * 16 + (i & 15));
    k1_load_chunk(sb, x, m0, 0, 0, t);
    k1_load_chunk(sb, x, m0, 1, 1, t);

    if (bx == 0) {
        for (int i = t; i < GG * HID; i += 256)
            d_g[i] = __int_as_float(0xff800000);     // -inf
    }

    const int lane = t & 31, cg = t >> 5;            // 4 nodes (lane+32j) x 8 cols (cg*8..)
    float acc[4][8];
    #pragma unroll
    for (int j = 0; j < 4; j++)
        #pragma unroll
        for (int c = 0; c < 8; c++) acc[j][c] = 0.f;

    for (int c = 0; c < 4; c++) {
        const int rem = 3 - c;
        if (rem >= 1) CP_WAIT(1); else CP_WAIT(0);
        __syncthreads();
        if (c + 2 < 4) k1_load_chunk(sb, x, m0, c + 2, (c + 2) % 3, t);

        const uint32_t xb = sb + K1_XB_OFF + (c % 3) * 16384;
        #pragma unroll
        for (int k4 = 0; k4 < 8; k4++) {
            float xv[4][4];
            #pragma unroll
            for (int j = 0; j < 4; j++) {
                const int n = lane + (j << 5);
                lds128f(xv[j], xb + (uint32_t)((n << 7) + ((k4 ^ (n & 7)) << 4)));
            }
            #pragma unroll
            for (int kk = 0; kk < 4; kk++) {
                const float4* wk = ws + (((c * 32 + (k4 << 2) + kk) << 4) + (cg << 1));
                const float4 w0 = wk[0];
                const float4 w1 = wk[1];
                #pragma unroll
                for (int j = 0; j < 4; j++) {
                    const float xs = xv[j][kk];
                    acc[j][0] += xs * w0.x;
                    acc[j][1] += xs * w0.y;
                    acc[j][2] += xs * w0.z;
                    acc[j][3] += xs * w0.w;
                    acc[j][4] += xs * w1.x;
                    acc[j][5] += xs * w1.y;
                    acc[j][6] += xs * w1.z;
                    acc[j][7] += xs * w1.w;
                }
            }
        }
        __syncthreads();
    }

    #pragma unroll
    for (int j = 0; j < 4; j++) {
        const int n = lane + (j << 5);
        #pragma unroll
        for (int c = 0; c < 8; c++)
            hs[(cg * 8 + c) * 136 + n] = __float2half_rn(acc[j][c]);
    }
    __syncthreads();

    const int lam = t & 31;
    for (int fbi = t >> 5; fbi < 32; fbi += 8) {
        const int cl = fbi >> 3, h16l = (fbi >> 1) & 3, g = fbi & 1;
        uint32_t v[4];
        #pragma unroll
        for (int j = 0; j < 4; j++) {
            int row = h16l * 16 + (lam >> 2) + ((j & 1) << 3);
            int kin = (g << 4) + ((lam & 3) << 1) + ((j >> 1) << 3);
            v[j] = *(const uint32_t*)(hs + row * 136 + cl * 32 + kin);
        }
        const int h16 = ch * 4 + h16l;
        const int chunk = mblk * 4 + cl;
        uint4* dst = (uint4*)(d_supTf + (size_t)chunk * 8192 + (size_t)((h16 * 2 + g) << 9) + (lam << 4));
        *dst = make_uint4(v[0], v[1], v[2], v[3]);
    }
}

// ====== Kernel 2: h^T = supT @ adj^T ; bias + leaky + segment-max (fused) ======
// Exact R13 structure (best: 282.7 total). A cp.async triple-buffer;
// B LDG fp32 -> cvt fp16 -> STS double-buffer; fp32-accumulate MMA.
#define A_STG     3
#define A_BYTES   16384                   // Kc=64 A fragments
#define B_STG     2
#define B_BYTES   16384                   // 128 nodes x 64k fp16
#define OFF_A     1024
#define OFF_B     (OFF_A + A_STG * A_BYTES)
#define SMEM_K2   (OFF_B + B_STG * B_BYTES)   // 83968
#define NSTAGE    256

__device__ __forceinline__ void issue_A(uint32_t sb, int s, int tid)
{
    const uint32_t aS = sb + OFF_A + (s % A_STG) * A_BYTES;
    const char* aG = (const char*)d_supTf + (size_t)s * A_BYTES;
    #pragma unroll
    for (int j = 0; j < 4; j++)
        cp16(aS + (uint32_t)((tid + (j << 8)) << 4), aG + ((tid + (j << 8)) << 4));
    CP_COMMIT();
}

__global__ void __launch_bounds__(256, 1)
gcn_gemm_pool(const float* __restrict__ adj, const float* __restrict__ b_gcn,
              const int* __restrict__ batch)
{
    extern __shared__ char smem[];
    const uint32_t sb = smem_u32(smem);
    const int tid = threadIdx.x;
    const int wid = tid >> 5, lid = tid & 31;
    const int wr = wid >> 2, wc = wid & 3;       // 2 x 4 warp grid
    const int m0 = blockIdx.x << 7;

    float4 breg[8];

    float acc[4][4][4];
    #pragma unroll
    for (int a = 0; a < 4; a++)
        #pragma unroll
        for (int b = 0; b < 4; b++)
            #pragma unroll
            for (int c = 0; c < 4; c++) acc[a][b][c] = 0.f;

    // prologue
    issue_A(sb, 0, tid);
    issue_A(sb, 1, tid);
    #pragma unroll
    for (int i = 0; i < 8; i++) {
        const int c = tid + (i << 8);
        const int r = c >> 4, q = c & 15;
        breg[i] = __ldg((const float4*)(adj + (size_t)(m0 + r) * NN + q * 4));
    }

    for (int s = 0; s < NSTAGE; s++) {
        // 1) stage B(s): cvt + STS from regs
        const uint32_t bS = sb + OFF_B + (s & 1) * B_BYTES;
        #pragma unroll
        for (int i = 0; i < 8; i++) {
            const int c = tid + (i << 8);
            const int r = c >> 4, q = c & 15;
            const uint32_t lo = packh2(breg[i].x, breg[i].y);
            const uint32_t hi = packh2(breg[i].z, breg[i].w);
            const uint32_t sw = (uint32_t)((r & 7) << 2);
            sts64(bS + (uint32_t)(r * 128) + ((((uint32_t)(2 * q)) ^ sw) << 2), lo, hi);
        }
        // 2) prefetch B(s+1) into regs
        if (s + 1 < NSTAGE) {
            #pragma unroll
            for (int i = 0; i < 8; i++) {
                const int c = tid + (i << 8);
                const int r = c >> 4, q = c & 15;
                breg[i] = __ldg((const float4*)(adj + (size_t)(m0 + r) * NN +
                                                (size_t)(s + 1) * 64 + q * 4));
            }
        }
        // 3) issue A(s+2)
        if (s + 2 < NSTAGE) issue_A(sb, s + 2, tid);
        // 4) A(s) must be resident; barrier also publishes B(s)
        const int rem = NSTAGE - 1 - s;
        if (rem >= 2)      CP_WAIT(2);
        else if (rem == 1) CP_WAIT(1);
        else               CP_WAIT(0);
        __syncthreads();

        // 5) compute
        const uint32_t aS = sb + OFF_A + (s % A_STG) * A_BYTES;
        #pragma unroll
        for (int ks = 0; ks < 4; ks++) {
            const int cch = ks >> 1, g = ks & 1;
            uint32_t afr[4][4];
            #pragma unroll
            for (int mt = 0; mt < 4; mt++)
                lds128(afr[mt], aS + (uint32_t)(cch * 8192 +
                       ((((wr * 4 + mt) * 2 + g) << 9) + (lid << 4))));
            const int p = (lid & 3) + (g << 3) + (cch << 4);
            uint32_t bfr[4][2];
            #pragma unroll
            for (int nt = 0; nt < 4; nt++) {
                const int mloc = wc * 32 + nt * 8 + (lid >> 2);
                const uint32_t sw = (uint32_t)((mloc & 7) << 2);
                const uint32_t rowb = bS + (uint32_t)(mloc * 128);
                bfr[nt][0] = lds32(rowb + ((((uint32_t)p) ^ sw) << 2));
                bfr[nt][1] = lds32(rowb + ((((uint32_t)(p + 4)) ^ sw) << 2));
            }
            #pragma unroll
            for (int mt = 0; mt < 4; mt++)
                #pragma unroll
                for (int nt = 0; nt < 4; nt++)
                    mma16816(acc[mt][nt], afr[mt], bfr[nt]);
        }
    }

    // epilogue: bias + leaky + segment-max (sign-split int atomics)
    #pragma unroll
    for (int nt = 0; nt < 4; nt++) {
        const int mA = m0 + wc * 32 + nt * 8 + 2 * (lid & 3);
        const int g0 = batch[mA] * HID;
        const int g1 = batch[mA + 1] * HID;
        #pragma unroll
        for (int mt = 0; mt < 4; mt++) {
            const int h0 = wr * 64 + mt * 16 + (lid >> 2);
            const float b0v = b_gcn[h0], b8v = b_gcn[h0 + 8];
            atomicMaxFloat(&d_g[g0 + h0],     leaky(acc[mt][nt][0] + b0v));
            atomicMaxFloat(&d_g[g1 + h0],     leaky(acc[mt][nt][1] + b0v));
            atomicMaxFloat(&d_g[g0 + h0 + 8], leaky(acc[mt][nt][2] + b8v));
            atomicMaxFloat(&d_g[g1 + h0 + 8], leaky(acc[mt][nt][3] + b8v));
        }
    }
}

// =============== Kernel 3: tiny MLP + head (vectorized, ILP) ===============
__global__ void __launch_bounds__(128)
mlp_head(const float* __restrict__ Wl1, const float* __restrict__ bl1,
         const float* __restrict__ Wl2, const float* __restrict__ bl2,
         const float* __restrict__ Wout, const float* __restrict__ bout,
         float* __restrict__ out)
{
    __shared__ float gin[128], h1[128], h2[128];
    const int i = blockIdx.x, t = threadIdx.x;
    gin[t] = d_g[i * HID + t];
    __syncthreads();

    {
        float a = bl1[t];
        const float4* w = (const float4*)(Wl1 + t * 128);
        const float4* g4 = (const float4*)gin;
        #pragma unroll
        for (int k4 = 0; k4 < 32; k4++) {
            const float4 wv = w[k4];
            const float4 gv = g4[k4];
            a += wv.x * gv.x;
            a += wv.y * gv.y;
            a += wv.z * gv.z;
            a += wv.w * gv.w;
        }
        h1[t] = leaky(a);
    }
    __syncthreads();

    {
        float b = bl2[t];
        const float4* w = (const float4*)(Wl2 + t * 128);
        const float4* g4 = (const float4*)h1;
        #pragma unroll
        for (int k4 = 0; k4 < 32; k4++) {
            const float4 wv = w[k4];
            const float4 gv = g4[k4];
            b += wv.x * gv.x;
            b += wv.y * gv.y;
            b += wv.z * gv.z;
            b += wv.w * gv.w;
        }
        h2[t] = leaky(b);
    }
    __syncthreads();

    if (t < 2) {
        float o = bout[t];
        const float4* w = (const float4*)(Wout + t * 128);
        const float4* g4 = (const float4*)h2;
        #pragma unroll
        for (int k4 = 0; k4 < 32; k4++) {
            const float4 wv = w[k4];
            const float4 gv = g4[k4];
            o += wv.x * gv.x;
            o += wv.y * gv.y;
            o += wv.z * gv.z;
            o += wv.w * gv.w;
        }
        out[i * 2 + t] = o;
    }
}

// =============== launch ===============
extern "C" void kernel_launch(void* const* d_in, const int* in_sizes, int n_in,
                              void* d_out, int out_size)
{
    const float* x    = (const float*)d_in[0];
    const float* adj  = (const float*)d_in[1];
    const float* Wg   = (const float*)d_in[2];
    const float* bg   = (const float*)d_in[3];
    const float* Wl1  = (const float*)d_in[4];
    const float* bl1  = (const float*)d_in[5];
    const float* Wl2  = (const float*)d_in[6];
    const float* bl2  = (const float*)d_in[7];
    const float* Wout = (const float*)d_in[8];
    const float* bout = (const float*)d_in[9];
    const int*   batch = (const int*)d_in[10];
    float* out = (float*)d_out;

    cudaFuncSetAttribute(gcn_support,   cudaFuncAttributeMaxDynamicSharedMemorySize, K1_SMEM);
    cudaFuncSetAttribute(gcn_gemm_pool, cudaFuncAttributeMaxDynamicSharedMemorySize, SMEM_K2);

    gcn_support<<<256, 256, K1_SMEM>>>(x, Wg);
    gcn_gemm_pool<<<128, 256, SMEM_K2>>>(adj, bg, batch);
    mlp_head<<<GG, 128>>>(Wl1, bl1, Wl2, bl2, Wout, bout, out);
}

// round 16
// speedup vs baseline: 1.1599x; 1.0060x over previous
#include <cuda_runtime.h>
#include <cuda_fp16.h>
#include <cstdint>
#include <cstddef>

#define NN 16384
#define HID 128
#define GG 64

// ---------- static scratch ----------
__device__ __align__(16) uint8_t d_supTf[(NN / 32) * 8192];  // 4 MB fp16 A fragments
__device__ float d_g[GG * HID];

// ---------- helpers ----------
__device__ __forceinline__ uint32_t smem_u32(const void* p) {
    uint32_t a;
    asm("{ .reg .u64 t; cvta.to.shared.u64 t, %1; cvt.u32.u64 %0, t; }" : "=r"(a) : "l"(p));
    return a;
}
__device__ __forceinline__ void cp16(uint32_t dst, const void* src) {
    asm volatile("cp.async.cg.shared.global [%0], [%1], 16;" :: "r"(dst), "l"(src) : "memory");
}
#define CP_COMMIT() asm volatile("cp.async.commit_group;" ::: "memory")
#define CP_WAIT(n)  asm volatile("cp.async.wait_group " #n ";" ::: "memory")

__device__ __forceinline__ void lds128(uint32_t* r, uint32_t a) {
    asm volatile("ld.shared.v4.b32 {%0,%1,%2,%3}, [%4];"
                 : "=r"(r[0]), "=r"(r[1]), "=r"(r[2]), "=r"(r[3]) : "r"(a));
}
__device__ __forceinline__ void lds128f(float* r, uint32_t a) {
    asm volatile("ld.shared.v4.f32 {%0,%1,%2,%3}, [%4];"
                 : "=f"(r[0]), "=f"(r[1]), "=f"(r[2]), "=f"(r[3]) : "r"(a));
}
__device__ __forceinline__ void lds128l(uint64_t* r, uint32_t a) {
    asm volatile("ld.shared.v2.b64 {%0,%1}, [%2];"
                 : "=l"(r[0]), "=l"(r[1]) : "r"(a));
}
__device__ __forceinline__ uint32_t lds32(uint32_t a) {
    uint32_t v;
    asm volatile("ld.shared.b32 %0, [%1];" : "=r"(v) : "r"(a));
    return v;
}
__device__ __forceinline__ void sts64(uint32_t a, uint32_t x, uint32_t y) {
    asm volatile("st.shared.v2.b32 [%0], {%1,%2};" :: "r"(a), "r"(x), "r"(y) : "memory");
}
__device__ __forceinline__ uint32_t packh2(float lo, float hi) {
    uint32_t d;
    asm("cvt.rn.f16x2.f32 %0, %1, %2;" : "=r"(d) : "f"(hi), "f"(lo));
    return d;
}
__device__ __forceinline__ uint64_t packf2(float lo, float hi) {
    uint64_t d;
    asm("mov.b64 %0, {%1, %2};" : "=l"(d) : "f"(lo), "f"(hi));
    return d;
}
__device__ __forceinline__ void fma2(uint64_t& acc, uint64_t w, uint64_t xs) {
    asm("fma.rn.f32x2 %0, %1, %2, %0;" : "+l"(acc) : "l"(w), "l"(xs));
}
__device__ __forceinline__ void unpackf2(float& lo, float& hi, uint64_t v) {
    asm("mov.b64 {%0, %1}, %2;" : "=f"(lo), "=f"(hi) : "l"(v));
}
__device__ __forceinline__ void mma16816(float* c, const uint32_t* a, const uint32_t* b) {
    asm volatile(
        "mma.sync.aligned.m16n8k16.row.col.f32.f16.f16.f32 "
        "{%0,%1,%2,%3}, {%4,%5,%6,%7}, {%8,%9}, {%0,%1,%2,%3};"
        : "+f"(c[0]), "+f"(c[1]), "+f"(c[2]), "+f"(c[3])
        : "r"(a[0]), "r"(a[1]), "r"(a[2]), "r"(a[3]), "r"(b[0]), "r"(b[1]));
}
__device__ __forceinline__ float leaky(float v) { return v > 0.f ? v : 0.01f * v; }
__device__ __forceinline__ void atomicMaxFloat(float* addr, float v) {
    if (v >= 0.f) atomicMax((int*)addr, __float_as_int(v));
    else          atomicMin((unsigned int*)addr, __float_as_uint(v));
}

// =============== Kernel 1: supT fp16 fragments = (x @ W_gcn)^T ===============
// R15 tiling (4 nodes x 8 cols per thread) + fma.rn.f32x2 packed math.
#define K1_WS_OFF   0
#define K1_XB_OFF   32768
#define K1_HS_OFF   (32768 + 3 * 16384)
#define K1_SMEM     (K1_HS_OFF + 64 * 136 * 2)    // 99328

__device__ __forceinline__ void k1_load_chunk(uint32_t sb, const float* __restrict__ x,
                                              int m0, int c, int buf, int tid)
{
    const uint32_t xb = sb + K1_XB_OFF + buf * 16384;
    #pragma unroll
    for (int j = 0; j < 4; j++) {
        int i = tid + (j << 8);            // 0..1023
        int r = i >> 3, q = i & 7;
        cp16(xb + (uint32_t)((r << 7) + ((q ^ (r & 7)) << 4)),
             x + (size_t)(m0 + r) * 128 + c * 32 + q * 4);
    }
    CP_COMMIT();
}

__global__ void __launch_bounds__(256, 2)
gcn_support(const float* __restrict__ x, const float* __restrict__ Wg)
{
    extern __shared__ char sm1[];
    const uint32_t sb = smem_u32(sm1);
    __half* hs = (__half*)(sm1 + K1_HS_OFF);         // [64 c][136 nodes]
    const int t = threadIdx.x;
    const int bx = blockIdx.x;
    const int mblk = bx >> 1, ch = bx & 1;
    const int m0 = mblk << 7;

    for (int i = t; i < 128 * 16; i += 256)
        cp16(sb + K1_WS_OFF + i * 16, (const float4*)Wg + (i >> 4) * 32 + ch * 16 + (i & 15));
    k1_load_chunk(sb, x, m0, 0, 0, t);
    k1_load_chunk(sb, x, m0, 1, 1, t);

    if (bx == 0) {
        for (int i = t; i < GG * HID; i += 256)
            d_g[i] = __int_as_float(0xff800000);     // -inf
    }

    const int lane = t & 31, cg = t >> 5;            // 4 nodes (lane+32j) x 8 cols (cg*8..)
    uint64_t acc2[4][4];                             // [node j][col pair p] packed f32x2
    #pragma unroll
    for (int j = 0; j < 4; j++)
        #pragma unroll
        for (int p = 0; p < 4; p++) acc2[j][p] = 0ull;

    for (int c = 0; c < 4; c++) {
        const int rem = 3 - c;
        if (rem >= 1) CP_WAIT(1); else CP_WAIT(0);
        __syncthreads();
        if (c + 2 < 4) k1_load_chunk(sb, x, m0, c + 2, (c + 2) % 3, t);

        const uint32_t xb = sb + K1_XB_OFF + (c % 3) * 16384;
        #pragma unroll
        for (int k4 = 0; k4 < 8; k4++) {
            float xv[4][4];
            #pragma unroll
            for (int j = 0; j < 4; j++) {
                const int n = lane + (j << 5);
                lds128f(xv[j], xb + (uint32_t)((n << 7) + ((k4 ^ (n & 7)) << 4)));
            }
            #pragma unroll
            for (int kk = 0; kk < 4; kk++) {
                // W row for this k, cols cg*8..cg*8+7 as 4 packed f32x2
                const uint32_t wadr = sb + K1_WS_OFF +
                    (uint32_t)((((c * 32 + (k4 << 2) + kk) << 4) + (cg << 1)) << 4);
                uint64_t w2[4];
                lds128l(w2,     wadr);
                lds128l(w2 + 2, wadr + 16);
                #pragma unroll
                for (int j = 0; j < 4; j++) {
                    const uint64_t xs2 = packf2(xv[j][kk], xv[j][kk]);
                    fma2(acc2[j][0], w2[0], xs2);
                    fma2(acc2[j][1], w2[1], xs2);
                    fma2(acc2[j][2], w2[2], xs2);
                    fma2(acc2[j][3], w2[3], xs2);
                }
            }
        }
        __syncthreads();
    }

    #pragma unroll
    for (int j = 0; j < 4; j++) {
        const int n = lane + (j << 5);
        #pragma unroll
        for (int p = 0; p < 4; p++) {
            float lo, hi;
            unpackf2(lo, hi, acc2[j][p]);
            hs[(cg * 8 + 2 * p + 0) * 136 + n] = __float2half_rn(lo);
            hs[(cg * 8 + 2 * p + 1) * 136 + n] = __float2half_rn(hi);
        }
    }
    __syncthreads();

    const int lam = t & 31;
    for (int fbi = t >> 5; fbi < 32; fbi += 8) {
        const int cl = fbi >> 3, h16l = (fbi >> 1) & 3, g = fbi & 1;
        uint32_t v[4];
        #pragma unroll
        for (int j = 0; j < 4; j++) {
            int row = h16l * 16 + (lam >> 2) + ((j & 1) << 3);
            int kin = (g << 4) + ((lam & 3) << 1) + ((j >> 1) << 3);
            v[j] = *(const uint32_t*)(hs + row * 136 + cl * 32 + kin);
        }
        const int h16 = ch * 4 + h16l;
        const int chunk = mblk * 4 + cl;
        uint4* dst = (uint4*)(d_supTf + (size_t)chunk * 8192 + (size_t)((h16 * 2 + g) << 9) + (lam << 4));
        *dst = make_uint4(v[0], v[1], v[2], v[3]);
    }
}

// ====== Kernel 2: h^T = supT @ adj^T ; bias + leaky + segment-max (fused) ======
// Exact R13 structure (best). A cp.async triple-buffer;
// B LDG fp32 -> cvt fp16 -> STS double-buffer; fp32-accumulate MMA.
#define A_STG     3
#define A_BYTES   16384                   // Kc=64 A fragments
#define B_STG     2
#define B_BYTES   16384                   // 128 nodes x 64k fp16
#define OFF_A     1024
#define OFF_B     (OFF_A + A_STG * A_BYTES)
#define SMEM_K2   (OFF_B + B_STG * B_BYTES)   // 83968
#define NSTAGE    256

__device__ __forceinline__ void issue_A(uint32_t sb, int s, int tid)
{
    const uint32_t aS = sb + OFF_A + (s % A_STG) * A_BYTES;
    const char* aG = (const char*)d_supTf + (size_t)s * A_BYTES;
    #pragma unroll
    for (int j = 0; j < 4; j++)
        cp16(aS + (uint32_t)((tid + (j << 8)) << 4), aG + ((tid + (j << 8)) << 4));
    CP_COMMIT();
}

__global__ void __launch_bounds__(256, 1)
gcn_gemm_pool(const float* __restrict__ adj, const float* __restrict__ b_gcn,
              const int* __restrict__ batch)
{
    extern __shared__ char smem[];
    const uint32_t sb = smem_u32(smem);
    const int tid = threadIdx.x;
    const int wid = tid >> 5, lid = tid & 31;
    const int wr = wid >> 2, wc = wid & 3;       // 2 x 4 warp grid
    const int m0 = blockIdx.x << 7;

    float4 breg[8];

    float acc[4][4][4];
    #pragma unroll
    for (int a = 0; a < 4; a++)
        #pragma unroll
        for (int b = 0; b < 4; b++)
            #pragma unroll
            for (int c = 0; c < 4; c++) acc[a][b][c] = 0.f;

    // prologue
    issue_A(sb, 0, tid);
    issue_A(sb, 1, tid);
    #pragma unroll
    for (int i = 0; i < 8; i++) {
        const int c = tid + (i << 8);
        const int r = c >> 4, q = c & 15;
        breg[i] = __ldg((const float4*)(adj + (size_t)(m0 + r) * NN + q * 4));
    }

    for (int s = 0; s < NSTAGE; s++) {
        // 1) stage B(s): cvt + STS from regs
        const uint32_t bS = sb + OFF_B + (s & 1) * B_BYTES;
        #pragma unroll
        for (int i = 0; i < 8; i++) {
            const int c = tid + (i << 8);
            const int r = c >> 4, q = c & 15;
            const uint32_t lo = packh2(breg[i].x, breg[i].y);
            const uint32_t hi = packh2(breg[i].z, breg[i].w);
            const uint32_t sw = (uint32_t)((r & 7) << 2);
            sts64(bS + (uint32_t)(r * 128) + ((((uint32_t)(2 * q)) ^ sw) << 2), lo, hi);
        }
        // 2) prefetch B(s+1) into regs
        if (s + 1 < NSTAGE) {
            #pragma unroll
            for (int i = 0; i < 8; i++) {
                const int c = tid + (i << 8);
                const int r = c >> 4, q = c & 15;
                breg[i] = __ldg((const float4*)(adj + (size_t)(m0 + r) * NN +
                                                (size_t)(s + 1) * 64 + q * 4));
            }
        }
        // 3) issue A(s+2)
        if (s + 2 < NSTAGE) issue_A(sb, s + 2, tid);
        // 4) A(s) must be resident; barrier also publishes B(s)
        const int rem = NSTAGE - 1 - s;
        if (rem >= 2)      CP_WAIT(2);
        else if (rem == 1) CP_WAIT(1);
        else               CP_WAIT(0);
        __syncthreads();

        // 5) compute
        const uint32_t aS = sb + OFF_A + (s % A_STG) * A_BYTES;
        #pragma unroll
        for (int ks = 0; ks < 4; ks++) {
            const int cch = ks >> 1, g = ks & 1;
            uint32_t afr[4][4];
            #pragma unroll
            for (int mt = 0; mt < 4; mt++)
                lds128(afr[mt], aS + (uint32_t)(cch * 8192 +
                       ((((wr * 4 + mt) * 2 + g) << 9) + (lid << 4))));
            const int p = (lid & 3) + (g << 3) + (cch << 4);
            uint32_t bfr[4][2];
            #pragma unroll
            for (int nt = 0; nt < 4; nt++) {
                const int mloc = wc * 32 + nt * 8 + (lid >> 2);
                const uint32_t sw = (uint32_t)((mloc & 7) << 2);
                const uint32_t rowb = bS + (uint32_t)(mloc * 128);
                bfr[nt][0] = lds32(rowb + ((((uint32_t)p) ^ sw) << 2));
                bfr[nt][1] = lds32(rowb + ((((uint32_t)(p + 4)) ^ sw) << 2));
            }
            #pragma unroll
            for (int mt = 0; mt < 4; mt++)
                #pragma unroll
                for (int nt = 0; nt < 4; nt++)
                    mma16816(acc[mt][nt], afr[mt], bfr[nt]);
        }
    }

    // epilogue: bias + leaky + segment-max (sign-split int atomics)
    #pragma unroll
    for (int nt = 0; nt < 4; nt++) {
        const int mA = m0 + wc * 32 + nt * 8 + 2 * (lid & 3);
        const int g0 = batch[mA] * HID;
        const int g1 = batch[mA + 1] * HID;
        #pragma unroll
        for (int mt = 0; mt < 4; mt++) {
            const int h0 = wr * 64 + mt * 16 + (lid >> 2);
            const float b0v = b_gcn[h0], b8v = b_gcn[h0 + 8];
            atomicMaxFloat(&d_g[g0 + h0],     leaky(acc[mt][nt][0] + b0v));
            atomicMaxFloat(&d_g[g1 + h0],     leaky(acc[mt][nt][1] + b0v));
            atomicMaxFloat(&d_g[g0 + h0 + 8], leaky(acc[mt][nt][2] + b8v));
            atomicMaxFloat(&d_g[g1 + h0 + 8], leaky(acc[mt][nt][3] + b8v));
        }
    }
}

// =============== Kernel 3: tiny MLP + head (vectorized, ILP) ===============
__global__ void __launch_bounds__(128)
mlp_head(const float* __restrict__ Wl1, const float* __restrict__ bl1,
         const float* __restrict__ Wl2, const float* __restrict__ bl2,
         const float* __restrict__ Wout, const float* __restrict__ bout,
         float* __restrict__ out)
{
    __shared__ float gin[128], h1[128], h2[128];
    const int i = blockIdx.x, t = threadIdx.x;
    gin[t] = d_g[i * HID + t];
    __syncthreads();

    {
        float a = bl1[t];
        const float4* w = (const float4*)(Wl1 + t * 128);
        const float4* g4 = (const float4*)gin;
        #pragma unroll
        for (int k4 = 0; k4 < 32; k4++) {
            const float4 wv = w[k4];
            const float4 gv = g4[k4];
            a += wv.x * gv.x;
            a += wv.y * gv.y;
            a += wv.z * gv.z;
            a += wv.w * gv.w;
        }
        h1[t] = leaky(a);
    }
    __syncthreads();

    {
        float b = bl2[t];
        const float4* w = (const float4*)(Wl2 + t * 128);
        const float4* g4 = (const float4*)h1;
        #pragma unroll
        for (int k4 = 0; k4 < 32; k4++) {
            const float4 wv = w[k4];
            const float4 gv = g4[k4];
            b += wv.x * gv.x;
            b += wv.y * gv.y;
            b += wv.z * gv.z;
            b += wv.w * gv.w;
        }
        h2[t] = leaky(b);
    }
    __syncthreads();

    if (t < 2) {
        float o = bout[t];
        const float4* w = (const float4*)(Wout + t * 128);
        const float4* g4 = (const float4*)h2;
        #pragma unroll
        for (int k4 = 0; k4 < 32; k4++) {
            const float4 wv = w[k4];
            const float4 gv = g4[k4];
            o += wv.x * gv.x;
            o += wv.y * gv.y;
            o += wv.z * gv.z;
            o += wv.w * gv.w;
        }
        out[i * 2 + t] = o;
    }
}

// =============== launch ===============
extern "C" void kernel_launch(void* const* d_in, const int* in_sizes, int n_in,
                              void* d_out, int out_size)
{
    const float* x    = (const float*)d_in[0];
    const float* adj  = (const float*)d_in[1];
    const float* Wg   = (const float*)d_in[2];
    const float* bg   = (const float*)d_in[3];
    const float* Wl1  = (const float*)d_in[4];
    const float* bl1  = (const float*)d_in[5];
    const float* Wl2  = (const float*)d_in[6];
    const float* bl2  = (const float*)d_in[7];
    const float* Wout = (const float*)d_in[8];
    const float* bout = (const float*)d_in[9];
    const int*   batch = (const int*)d_in[10];
    float* out = (float*)d_out;

    cudaFuncSetAttribute(gcn_support,   cudaFuncAttributeMaxDynamicSharedMemorySize, K1_SMEM);
    cudaFuncSetAttribute(gcn_gemm_pool, cudaFuncAttributeMaxDynamicSharedMemorySize, SMEM_K2);

    gcn_support<<<256, 256, K1_SMEM>>>(x, Wg);
    gcn_gemm_pool<<<128, 256, SMEM_K2>>>(adj, bg, batch);
    mlp_head<<<GG, 128>>>(Wl1, bl1, Wl2, bl2, Wout, bout, out);
}

// round 17
// speedup vs baseline: 1.2125x; 1.0453x over previous
#include <cuda_runtime.h>
#include <cuda_fp16.h>
#include <cstdint>
#include <cstddef>

#define NN 16384
#define HID 128
#define GG 64

// ---------- static scratch ----------
__device__ __align__(16) uint8_t d_supTf[(NN / 32) * 8192];  // 4 MB fp16 A fragments
__device__ __align__(16) float d_h[NN * HID];                // 8 MB partial sums
__device__ float d_g[GG * HID];

// ---------- helpers ----------
__device__ __forceinline__ uint32_t smem_u32(const void* p) {
    uint32_t a;
    asm("{ .reg .u64 t; cvta.to.shared.u64 t, %1; cvt.u32.u64 %0, t; }" : "=r"(a) : "l"(p));
    return a;
}
__device__ __forceinline__ void cp16(uint32_t dst, const void* src) {
    asm volatile("cp.async.cg.shared.global [%0], [%1], 16;" :: "r"(dst), "l"(src) : "memory");
}
#define CP_COMMIT() asm volatile("cp.async.commit_group;" ::: "memory")
#define CP_WAIT(n)  asm volatile("cp.async.wait_group " #n ";" ::: "memory")

__device__ __forceinline__ void lds128(uint32_t* r, uint32_t a) {
    asm volatile("ld.shared.v4.b32 {%0,%1,%2,%3}, [%4];"
                 : "=r"(r[0]), "=r"(r[1]), "=r"(r[2]), "=r"(r[3]) : "r"(a));
}
__device__ __forceinline__ void lds128f(float* r, uint32_t a) {
    asm volatile("ld.shared.v4.f32 {%0,%1,%2,%3}, [%4];"
                 : "=f"(r[0]), "=f"(r[1]), "=f"(r[2]), "=f"(r[3]) : "r"(a));
}
__device__ __forceinline__ void lds128l(uint64_t* r, uint32_t a) {
    asm volatile("ld.shared.v2.b64 {%0,%1}, [%2];"
                 : "=l"(r[0]), "=l"(r[1]) : "r"(a));
}
__device__ __forceinline__ uint32_t lds32(uint32_t a) {
    uint32_t v;
    asm volatile("ld.shared.b32 %0, [%1];" : "=r"(v) : "r"(a));
    return v;
}
__device__ __forceinline__ void sts64(uint32_t a, uint32_t x, uint32_t y) {
    asm volatile("st.shared.v2.b32 [%0], {%1,%2};" :: "r"(a), "r"(x), "r"(y) : "memory");
}
__device__ __forceinline__ uint32_t packh2(float lo, float hi) {
    uint32_t d;
    asm("cvt.rn.f16x2.f32 %0, %1, %2;" : "=r"(d) : "f"(hi), "f"(lo));
    return d;
}
__device__ __forceinline__ uint64_t packf2(float lo, float hi) {
    uint64_t d;
    asm("mov.b64 %0, {%1, %2};" : "=l"(d) : "f"(lo), "f"(hi));
    return d;
}
__device__ __forceinline__ void fma2(uint64_t& acc, uint64_t w, uint64_t xs) {
    asm("fma.rn.f32x2 %0, %1, %2, %0;" : "+l"(acc) : "l"(w), "l"(xs));
}
__device__ __forceinline__ void unpackf2(float& lo, float& hi, uint64_t v) {
    asm("mov.b64 {%0, %1}, %2;" : "=f"(lo), "=f"(hi) : "l"(v));
}
__device__ __forceinline__ void mma16816(float* c, const uint32_t* a, const uint32_t* b) {
    asm volatile(
        "mma.sync.aligned.m16n8k16.row.col.f32.f16.f16.f32 "
        "{%0,%1,%2,%3}, {%4,%5,%6,%7}, {%8,%9}, {%0,%1,%2,%3};"
        : "+f"(c[0]), "+f"(c[1]), "+f"(c[2]), "+f"(c[3])
        : "r"(a[0]), "r"(a[1]), "r"(a[2]), "r"(a[3]), "r"(b[0]), "r"(b[1]));
}
__device__ __forceinline__ float leaky(float v) { return v > 0.f ? v : 0.01f * v; }
__device__ __forceinline__ void atomicMaxFloat(float* addr, float v) {
    if (v >= 0.f) atomicMax((int*)addr, __float_as_int(v));
    else          atomicMin((unsigned int*)addr, __float_as_uint(v));
}
__device__ __forceinline__ void atomicMaxFloatS(int* addr, float v) {
    if (v >= 0.f) atomicMax(addr, __float_as_int(v));
    else          atomicMin((unsigned int*)addr, __float_as_uint(v));
}

// =============== Kernel 1: supT fp16 fragments = (x @ W_gcn)^T ===============
// R16 exact (f32x2, 17.0 us) + d_h clear.
#define K1_WS_OFF   0
#define K1_XB_OFF   32768
#define K1_HS_OFF   (32768 + 3 * 16384)
#define K1_SMEM     (K1_HS_OFF + 64 * 136 * 2)    // 99328

__device__ __forceinline__ void k1_load_chunk(uint32_t sb, const float* __restrict__ x,
                                              int m0, int c, int buf, int tid)
{
    const uint32_t xb = sb + K1_XB_OFF + buf * 16384;
    #pragma unroll
    for (int j = 0; j < 4; j++) {
        int i = tid + (j << 8);            // 0..1023
        int r = i >> 3, q = i & 7;
        cp16(xb + (uint32_t)((r << 7) + ((q ^ (r & 7)) << 4)),
             x + (size_t)(m0 + r) * 128 + c * 32 + q * 4);
    }
    CP_COMMIT();
}

__global__ void __launch_bounds__(256, 2)
gcn_support(const float* __restrict__ x, const float* __restrict__ Wg)
{
    extern __shared__ char sm1[];
    const uint32_t sb = smem_u32(sm1);
    __half* hs = (__half*)(sm1 + K1_HS_OFF);         // [64 c][136 nodes]
    const int t = threadIdx.x;
    const int bx = blockIdx.x;
    const int mblk = bx >> 1, ch = bx & 1;
    const int m0 = mblk << 7;

    for (int i = t; i < 128 * 16; i += 256)
        cp16(sb + K1_WS_OFF + i * 16, (const float4*)Wg + (i >> 4) * 32 + ch * 16 + (i & 15));
    k1_load_chunk(sb, x, m0, 0, 0, t);
    k1_load_chunk(sb, x, m0, 1, 1, t);

    // clear d_h (8192 floats per block) and init d_g
    {
        float4 z = make_float4(0.f, 0.f, 0.f, 0.f);
        #pragma unroll
        for (int i = 0; i < 8; i++)
            ((float4*)d_h)[bx * 2048 + i * 256 + t] = z;
    }
    if (bx == 0) {
        for (int i = t; i < GG * HID; i += 256)
            d_g[i] = __int_as_float(0xff800000);     // -inf
    }

    const int lane = t & 31, cg = t >> 5;            // 4 nodes (lane+32j) x 8 cols (cg*8..)
    uint64_t acc2[4][4];
    #pragma unroll
    for (int j = 0; j < 4; j++)
        #pragma unroll
        for (int p = 0; p < 4; p++) acc2[j][p] = 0ull;

    for (int c = 0; c < 4; c++) {
        const int rem = 3 - c;
        if (rem >= 1) CP_WAIT(1); else CP_WAIT(0);
        __syncthreads();
        if (c + 2 < 4) k1_load_chunk(sb, x, m0, c + 2, (c + 2) % 3, t);

        const uint32_t xb = sb + K1_XB_OFF + (c % 3) * 16384;
        #pragma unroll
        for (int k4 = 0; k4 < 8; k4++) {
            float xv[4][4];
            #pragma unroll
            for (int j = 0; j < 4; j++) {
                const int n = lane + (j << 5);
                lds128f(xv[j], xb + (uint32_t)((n << 7) + ((k4 ^ (n & 7)) << 4)));
            }
            #pragma unroll
            for (int kk = 0; kk < 4; kk++) {
                const uint32_t wadr = sb + K1_WS_OFF +
                    (uint32_t)((((c * 32 + (k4 << 2) + kk) << 4) + (cg << 1)) << 4);
                uint64_t w2[4];
                lds128l(w2,     wadr);
                lds128l(w2 + 2, wadr + 16);
                #pragma unroll
                for (int j = 0; j < 4; j++) {
                    const uint64_t xs2 = packf2(xv[j][kk], xv[j][kk]);
                    fma2(acc2[j][0], w2[0], xs2);
                    fma2(acc2[j][1], w2[1], xs2);
                    fma2(acc2[j][2], w2[2], xs2);
                    fma2(acc2[j][3], w2[3], xs2);
                }
            }
        }
        __syncthreads();
    }

    #pragma unroll
    for (int j = 0; j < 4; j++) {
        const int n = lane + (j << 5);
        #pragma unroll
        for (int p = 0; p < 4; p++) {
            float lo, hi;
            unpackf2(lo, hi, acc2[j][p]);
            hs[(cg * 8 + 2 * p + 0) * 136 + n] = __float2half_rn(lo);
            hs[(cg * 8 + 2 * p + 1) * 136 + n] = __float2half_rn(hi);
        }
    }
    __syncthreads();

    const int lam = t & 31;
    for (int fbi = t >> 5; fbi < 32; fbi += 8) {
        const int cl = fbi >> 3, h16l = (fbi >> 1) & 3, g = fbi & 1;
        uint32_t v[4];
        #pragma unroll
        for (int j = 0; j < 4; j++) {
            int row = h16l * 16 + (lam >> 2) + ((j & 1) << 3);
            int kin = (g << 4) + ((lam & 3) << 1) + ((j >> 1) << 3);
            v[j] = *(const uint32_t*)(hs + row * 136 + cl * 32 + kin);
        }
        const int h16 = ch * 4 + h16l;
        const int chunk = mblk * 4 + cl;
        uint4* dst = (uint4*)(d_supTf + (size_t)chunk * 8192 + (size_t)((h16 * 2 + g) << 9) + (lam << 4));
        *dst = make_uint4(v[0], v[1], v[2], v[3]);
    }
}

// ====== Kernel 2: h partials = supT @ adj^T, even split over 148 CTAs ======
// R12's proven split structure with R10 mainloop internals.
#define A_STG     3
#define A_BYTES   16384
#define B_STG     2
#define B_BYTES   16384
#define OFF_A     1024
#define OFF_B     (OFF_A + A_STG * A_BYTES)
#define SMEM_K2   (OFF_B + B_STG * B_BYTES)   // 83968
#define TOTC      32768
#define NCTA      148

__device__ __forceinline__ void issue_A(uint32_t sb, int kc, int buf, int tid)
{
    const uint32_t aS = sb + OFF_A + buf * A_BYTES;
    const char* aG = (const char*)d_supTf + (size_t)kc * A_BYTES;
    #pragma unroll
    for (int j = 0; j < 4; j++)
        cp16(aS + (uint32_t)((tid + (j << 8)) << 4), aG + ((tid + (j << 8)) << 4));
    CP_COMMIT();
}

__global__ void __launch_bounds__(256, 1)
gcn_gemm_pool(const float* __restrict__ adj)
{
    extern __shared__ char smem[];
    const uint32_t sb = smem_u32(smem);
    const int tid = threadIdx.x;
    const int wid = tid >> 5, lid = tid & 31;
    const int wr = wid >> 2, wc = wid & 3;

    const int c0 = (int)(((long long)TOTC * blockIdx.x) / NCTA);
    const int c1 = (int)(((long long)TOTC * (blockIdx.x + 1)) / NCTA);
    const int len = c1 - c0;

    float4 breg[8];

    float acc[4][4][4];
    #pragma unroll
    for (int a = 0; a < 4; a++)
        #pragma unroll
        for (int b = 0; b < 4; b++)
            #pragma unroll
            for (int c = 0; c < 4; c++) acc[a][b][c] = 0.f;

    issue_A(sb, c0 & 255, 0, tid);
    issue_A(sb, (c0 + 1) & 255, 1, tid);
    {
        const int m0 = (c0 >> 8) << 7, kc = c0 & 255;
        #pragma unroll
        for (int i = 0; i < 8; i++) {
            const int c = tid + (i << 8);
            const int r = c >> 4, q = c & 15;
            breg[i] = __ldg((const float4*)(adj + (size_t)(m0 + r) * NN + kc * 64 + q * 4));
        }
    }

    for (int j = 0; j < len; j++) {
        const int c = c0 + j;
        const int tile = c >> 8;
        const uint32_t bS = sb + OFF_B + (j & 1) * B_BYTES;
        #pragma unroll
        for (int i = 0; i < 8; i++) {
            const int cc = tid + (i << 8);
            const int r = cc >> 4, q = cc & 15;
            const uint32_t lo = packh2(breg[i].x, breg[i].y);
            const uint32_t hi = packh2(breg[i].z, breg[i].w);
            const uint32_t sw = (uint32_t)((r & 7) << 2);
            sts64(bS + (uint32_t)(r * 128) + ((((uint32_t)(2 * q)) ^ sw) << 2), lo, hi);
        }
        if (j + 1 < len) {
            const int cn = c + 1;
            const int m0n = (cn >> 8) << 7, kcn = cn & 255;
            #pragma unroll
            for (int i = 0; i < 8; i++) {
                const int cc = tid + (i << 8);
                const int r = cc >> 4, q = cc & 15;
                breg[i] = __ldg((const float4*)(adj + (size_t)(m0n + r) * NN + kcn * 64 + q * 4));
            }
        }
        if (j + 2 < len) CP_WAIT(1); else CP_WAIT(0);
        __syncthreads();
        if (j + 2 < len) issue_A(sb, (c + 2) & 255, (j + 2) % 3, tid);

        const uint32_t aS = sb + OFF_A + (j % 3) * A_BYTES;
        #pragma unroll
        for (int ks = 0; ks < 4; ks++) {
            const int cch = ks >> 1, g = ks & 1;
            uint32_t afr[4][4];
            #pragma unroll
            for (int mt = 0; mt < 4; mt++)
                lds128(afr[mt], aS + (uint32_t)(cch * 8192 +
                       ((((wr * 4 + mt) * 2 + g) << 9) + (lid << 4))));
            const int p = (lid & 3) + (g << 3) + (cch << 4);
            uint32_t bfr[4][2];
            #pragma unroll
            for (int nt = 0; nt < 4; nt++) {
                const int mloc = wc * 32 + nt * 8 + (lid >> 2);
                const uint32_t sw = (uint32_t)((mloc & 7) << 2);
                const uint32_t rowb = bS + (uint32_t)(mloc * 128);
                bfr[nt][0] = lds32(rowb + ((((uint32_t)p) ^ sw) << 2));
                bfr[nt][1] = lds32(rowb + ((((uint32_t)(p + 4)) ^ sw) << 2));
            }
            #pragma unroll
            for (int mt = 0; mt < 4; mt++)
                #pragma unroll
                for (int nt = 0; nt < 4; nt++)
                    mma16816(acc[mt][nt], afr[mt], bfr[nt]);
        }

        // flush at tile crossing / end
        if (j + 1 == len || ((c + 1) >> 8) != tile) {
            const int m0 = tile << 7;
            #pragma unroll
            for (int nt = 0; nt < 4; nt++) {
                const int mA = m0 + wc * 32 + nt * 8 + 2 * (lid & 3);
                #pragma unroll
                for (int mt = 0; mt < 4; mt++) {
                    const int h0 = wr * 64 + mt * 16 + (lid >> 2);
                    atomicAdd(&d_h[(size_t)mA * HID + h0],           acc[mt][nt][0]);
                    atomicAdd(&d_h[(size_t)(mA + 1) * HID + h0],     acc[mt][nt][1]);
                    atomicAdd(&d_h[(size_t)mA * HID + h0 + 8],       acc[mt][nt][2]);
                    atomicAdd(&d_h[(size_t)(mA + 1) * HID + h0 + 8], acc[mt][nt][3]);
                    acc[mt][nt][0] = acc[mt][nt][1] = acc[mt][nt][2] = acc[mt][nt][3] = 0.f;
                }
            }
        }
    }
}

// === Kernel 2b: bias + leaky + segment-max via SMEM reduction (sorted batch) ===
__global__ void __launch_bounds__(256)
gcn_pool(const float* __restrict__ b_gcn, const int* __restrict__ batch)
{
    __shared__ int smax[GG * HID];   // 32 KB worst case
    const int t = threadIdx.x;
    const int n0 = blockIdx.x * 128;
    const int g_lo = batch[n0];
    const int g_hi = batch[n0 + 127];
    const int R = g_hi - g_lo + 1;

    for (int i = t; i < R * HID; i += 256) smax[i] = 0xff800000;
    __syncthreads();

    const int node = n0 + (t >> 1);
    const int hb = (t & 1) * 64;
    const int gl = (batch[node] - g_lo) * HID + hb;
    const float* hrow = d_h + (size_t)node * HID + hb;
    #pragma unroll
    for (int jj = 0; jj < 16; jj++) {
        const float4 v = ((const float4*)hrow)[jj];
        const float4 b = ((const float4*)(b_gcn + hb))[jj];
        atomicMaxFloatS(&smax[gl + 4 * jj + 0], leaky(v.x + b.x));
        atomicMaxFloatS(&smax[gl + 4 * jj + 1], leaky(v.y + b.y));
        atomicMaxFloatS(&smax[gl + 4 * jj + 2], leaky(v.z + b.z));
        atomicMaxFloatS(&smax[gl + 4 * jj + 3], leaky(v.w + b.w));
    }
    __syncthreads();

    for (int i = t; i < R * HID; i += 256) {
        const int bits = smax[i];
        if (bits != (int)0xff800000)
            atomicMaxFloat(&d_g[(g_lo + i / HID) * HID + (i % HID)], __int_as_float(bits));
    }
}

// =============== Kernel 3: tiny MLP + head (vectorized, ILP) ===============
__global__ void __launch_bounds__(128)
mlp_head(const float* __restrict__ Wl1, const float* __restrict__ bl1,
         const float* __restrict__ Wl2, const float* __restrict__ bl2,
         const float* __restrict__ Wout, const float* __restrict__ bout,
         float* __restrict__ out)
{
    __shared__ float gin[128], h1[128], h2[128];
    const int i = blockIdx.x, t = threadIdx.x;
    gin[t] = d_g[i * HID + t];
    __syncthreads();

    {
        float a = bl1[t];
        const float4* w = (const float4*)(Wl1 + t * 128);
        const float4* g4 = (const float4*)gin;
        #pragma unroll
        for (int k4 = 0; k4 < 32; k4++) {
            const float4 wv = w[k4];
            const float4 gv = g4[k4];
            a += wv.x * gv.x; a += wv.y * gv.y; a += wv.z * gv.z; a += wv.w * gv.w;
        }
        h1[t] = leaky(a);
    }
    __syncthreads();

    {
        float b = bl2[t];
        const float4* w = (const float4*)(Wl2 + t * 128);
        const float4* g4 = (const float4*)h1;
        #pragma unroll
        for (int k4 = 0; k4 < 32; k4++) {
            const float4 wv = w[k4];
            const float4 gv = g4[k4];
            b += wv.x * gv.x; b += wv.y * gv.y; b += wv.z * gv.z; b += wv.w * gv.w;
        }
        h2[t] = leaky(b);
    }
    __syncthreads();

    if (t < 2) {
        float o = bout[t];
        const float4* w = (const float4*)(Wout + t * 128);
        const float4* g4 = (const float4*)h2;
        #pragma unroll
        for (int k4 = 0; k4 < 32; k4++) {
            const float4 wv = w[k4];
            const float4 gv = g4[k4];
            o += wv.x * gv.x; o += wv.y * gv.y; o += wv.z * gv.z; o += wv.w * gv.w;
        }
        out[i * 2 + t] = o;
    }
}

// =============== launch ===============
extern "C" void kernel_launch(void* const* d_in, const int* in_sizes, int n_in,
                              void* d_out, int out_size)
{
    const float* x    = (const float*)d_in[0];
    const float* adj  = (const float*)d_in[1];
    const float* Wg   = (const float*)d_in[2];
    const float* bg   = (const float*)d_in[3];
    const float* Wl1  = (const float*)d_in[4];
    const float* bl1  = (const float*)d_in[5];
    const float* Wl2  = (const float*)d_in[6];
    const float* bl2  = (const float*)d_in[7];
    const float* Wout = (const float*)d_in[8];
    const float* bout = (const float*)d_in[9];
    const int*   batch = (const int*)d_in[10];
    float* out = (float*)d_out;

    cudaFuncSetAttribute(gcn_support,   cudaFuncAttributeMaxDynamicSharedMemorySize, K1_SMEM);
    cudaFuncSetAttribute(gcn_gemm_pool, cudaFuncAttributeMaxDynamicSharedMemorySize, SMEM_K2);

    gcn_support<<<256, 256, K1_SMEM>>>(x, Wg);
    gcn_gemm_pool<<<NCTA, 256, SMEM_K2>>>(adj);
    gcn_pool<<<128, 256>>>(bg, batch);
    mlp_head<<<GG, 128>>>(Wl1, bl1, Wl2, bl2, Wout, bout, out);
}